// round 6
// baseline (speedup 1.0000x reference)
#include <cuda_runtime.h>
#include <math.h>

#define N_NODES 50000
#define N_EDGES 800000
#define HEADS   8
#define ODIM    8
#define HDIM    64
#define CLAMP_V 5.0f
#define EPS_V   1e-8f
#define TILES   (N_EDGES / 32)      // 25000 tiles of 32 edges
#define EDGE_GRID 444               // 148 SMs * 3 persistent blocks

#define W_STRIDE  68                // sWT row stride in floats (272B, 16B-aligned)
#define EA_STRIDE 68                // sEA row stride (attrs, then scores)
#define SMEM_WT_FLOATS (128 * W_STRIDE)
#define SMEM_EDGE_BYTES ((SMEM_WT_FLOATS + 32 * EA_STRIDE) * 4)   // 43520

// ---------------- device scratch ----------------
__device__ __align__(16) float g_Qh[N_NODES * HDIM];
__device__ __align__(16) float g_Kh[N_NODES * HDIM];
__device__ __align__(16) float g_Vh[N_NODES * HDIM];
__device__ __align__(16) float g_den[N_NODES * HEADS];
__device__ __align__(16) float g_wV  [N_NODES * HDIM];
__device__ __align__(16) float g_rowV[N_NODES * HDIM];
__device__ unsigned g_orhigh;

// ---------------- helpers ----------------
__device__ __forceinline__ void redAddV4(float* p, float a, float b, float c, float d) {
    asm volatile("red.global.add.v4.f32 [%0], {%1,%2,%3,%4};"
                 :: "l"(p), "f"(a), "f"(b), "f"(c), "f"(d) : "memory");
}
__device__ __forceinline__ void ffma2(unsigned long long& acc,
                                      unsigned long long a, unsigned long long b) {
    asm("fma.rn.f32x2 %0, %1, %2, %0;" : "+l"(acc) : "l"(a), "l"(b));
}
__device__ __forceinline__ unsigned long long pack2(float lo, float hi) {
    unsigned long long r;
    asm("mov.b64 %0, {%1,%2};" : "=l"(r) : "f"(lo), "f"(hi));
    return r;
}
__device__ __forceinline__ float sum2(unsigned long long v) {
    float2 r;
    asm("mov.b64 {%0,%1}, %2;" : "=f"(r.x), "=f"(r.y) : "l"(v));
    return r.x + r.y;
}
__device__ __forceinline__ float signed_sqrt(float x) {
    return sqrtf(fmaxf(x, 0.0f) + EPS_V) - sqrtf(fmaxf(-x, 0.0f) + EPS_V);
}

// ---------------- kernel 0: init accumulators + dtype flag ----------------
__global__ void k_init() {
    int i = blockIdx.x * blockDim.x + threadIdx.x;
    float4 z = make_float4(0.f, 0.f, 0.f, 0.f);
    if (i < N_NODES * HDIM / 4) {
        reinterpret_cast<float4*>(g_wV)[i] = z;
        reinterpret_cast<float4*>(g_rowV)[i] = z;
    }
    if (i < N_NODES * HEADS / 4) reinterpret_cast<float4*>(g_den)[i] = z;
    if (i == 0) g_orhigh = 0u;
}

// ---------------- kernel 1: index dtype detection ----------------
// int64 input: high words of all 800k int64s are 0 -> OR stays 0.
// int32 input: odd 32-bit words are random node ids -> OR != 0.
__global__ void k_detect(const unsigned* __restrict__ raw) {
    int i = blockIdx.x * blockDim.x + threadIdx.x;
    unsigned hi = (i < N_EDGES) ? raw[2 * i + 1] : 0u;
    hi = __reduce_or_sync(0xffffffffu, hi);
    if ((threadIdx.x & 31) == 0 && hi) atomicOr(&g_orhigh, hi);
}

// ---------------- kernel 2: node projections Q,K,V ----------------
__global__ void k_nodeproj(const float* __restrict__ x,
                           const float* __restrict__ Wq, const float* __restrict__ bq,
                           const float* __restrict__ Wk, const float* __restrict__ bk,
                           const float* __restrict__ Wv, const float* __restrict__ bv) {
    __shared__ float sW[64 * 64];
    __shared__ float sA[8][4][64];
    const int tid = threadIdx.x, warp = tid >> 5, lane = tid & 31;
    const int n0 = (blockIdx.x * 8 + warp) * 4;

    #pragma unroll
    for (int n = 0; n < 4; n++) {
        int node = n0 + n; if (node >= N_NODES) node = N_NODES - 1;
        sA[warp][n][lane]      = x[(size_t)node * 64 + lane];
        sA[warp][n][lane + 32] = x[(size_t)node * 64 + lane + 32];
    }

#define PROJ(W, B, OUT) do {                                                  \
    __syncthreads();                                                          \
    for (int i = tid; i < 4096; i += 256) sW[i] = (W)[i];                     \
    __syncthreads();                                                          \
    float b0 = (B)[lane], b1 = (B)[lane + 32];                                \
    float a0c0 = b0, a0c1 = b1, a1c0 = b0, a1c1 = b1;                         \
    float a2c0 = b0, a2c1 = b1, a3c0 = b0, a3c1 = b1;                         \
    _Pragma("unroll 16")                                                      \
    for (int k = 0; k < 64; k++) {                                            \
        float w0 = sW[k * 64 + lane], w1 = sW[k * 64 + lane + 32];            \
        float a0 = sA[warp][0][k], a1 = sA[warp][1][k];                       \
        float a2 = sA[warp][2][k], a3 = sA[warp][3][k];                       \
        a0c0 = fmaf(a0, w0, a0c0); a0c1 = fmaf(a0, w1, a0c1);                 \
        a1c0 = fmaf(a1, w0, a1c0); a1c1 = fmaf(a1, w1, a1c1);                 \
        a2c0 = fmaf(a2, w0, a2c0); a2c1 = fmaf(a2, w1, a2c1);                 \
        a3c0 = fmaf(a3, w0, a3c0); a3c1 = fmaf(a3, w1, a3c1);                 \
    }                                                                         \
    if (n0 + 0 < N_NODES) { (OUT)[(size_t)(n0+0)*64+lane]=a0c0; (OUT)[(size_t)(n0+0)*64+lane+32]=a0c1; } \
    if (n0 + 1 < N_NODES) { (OUT)[(size_t)(n0+1)*64+lane]=a1c0; (OUT)[(size_t)(n0+1)*64+lane+32]=a1c1; } \
    if (n0 + 2 < N_NODES) { (OUT)[(size_t)(n0+2)*64+lane]=a2c0; (OUT)[(size_t)(n0+2)*64+lane+32]=a2c1; } \
    if (n0 + 3 < N_NODES) { (OUT)[(size_t)(n0+3)*64+lane]=a3c0; (OUT)[(size_t)(n0+3)*64+lane+32]=a3c1; } \
} while (0)

    PROJ(Wq, bq, g_Qh);
    PROJ(Wk, bk, g_Kh);
    PROJ(Wv, bv, g_Vh);
#undef PROJ
}

// ---------------- kernel 3: fused edge kernel ----------------
// Per tile (4 edges/warp): prefetch indices + Kh/Qh lane values BEFORE the
// GEMM so L2 gather latency hides under ~2000 cycles of FFMA2 work.
// GEMM: FFMA2 lanes = (even-k, odd-k) partial sums; lane computes exactly its
// phase-B columns cw, cw+8, cw+64, cw+72 (cw=(lane>>3)*16+(lane&7)).
__global__ void __launch_bounds__(256, 3)
k_edge(const float* __restrict__ edge_attr,
       const void* __restrict__ ei_raw,
       const float* __restrict__ We, const float* __restrict__ be,
       const float* __restrict__ Aw,
       float* __restrict__ wE_out) {
    extern __shared__ float smem[];
    float* sWT = smem;                        // [128][W_STRIDE], sWT[c][k]=We[k][c]
    float* sEA = smem + SMEM_WT_FLOATS;       // [32][EA_STRIDE]: attrs -> scores
    __shared__ float sP[8][4][8];             // exp(s) per (warp, edge, head)

    const int tid = threadIdx.x, warp = tid >> 5, lane = tid & 31;
    const int e_loc0 = warp * 4;

    // one-time: transpose We into sWT
    for (int i = tid; i < 128 * 64; i += 256) {
        int c = i & 127, k = i >> 7;
        sWT[c * W_STRIDE + k] = We[k * 128 + c];
    }
    __syncthreads();

    const int d0 = lane & 7, h0 = lane >> 3;
    const int cw = (h0 << 4) + d0;
    const float aw0 = Aw[d0 * 8 + h0];
    const float aw1 = Aw[d0 * 8 + h0 + 4];

    const unsigned long long bini0 = pack2(be[cw],      0.f);
    const unsigned long long bini1 = pack2(be[cw + 8],  0.f);
    const unsigned long long bini2 = pack2(be[cw + 64], 0.f);
    const unsigned long long bini3 = pack2(be[cw + 72], 0.f);

    const float* wrow0 = &sWT[(cw)      * W_STRIDE];
    const float* wrow1 = &sWT[(cw + 8)  * W_STRIDE];
    const float* wrow2 = &sWT[(cw + 64) * W_STRIDE];
    const float* wrow3 = &sWT[(cw + 72) * W_STRIDE];

    const bool idx64 = (g_orhigh == 0u);
    const long long* p64 = (const long long*)ei_raw;
    const int*       p32 = (const int*)ei_raw;

    for (int tile = blockIdx.x; tile < TILES; tile += gridDim.x) {
        const int e0 = tile * 32 + e_loc0;

        // ---- prefetch: indices, then Kh/Qh lane values (cover with GEMM) ----
        int srcs[4], dsts[4];
        if (idx64) {
            #pragma unroll
            for (int n = 0; n < 4; n++) {
                srcs[n] = (int)__ldg(&p64[e0 + n]);
                dsts[n] = (int)__ldg(&p64[N_EDGES + e0 + n]);
            }
        } else {
            #pragma unroll
            for (int n = 0; n < 4; n++) {
                srcs[n] = __ldg(&p32[e0 + n]);
                dsts[n] = __ldg(&p32[N_EDGES + e0 + n]);
            }
        }
        float khA[4], khB[4], qhA[4], qhB[4];
        #pragma unroll
        for (int n = 0; n < 4; n++) {
            khA[n] = __ldg(&g_Kh[(size_t)srcs[n] * 64 + lane]);
            khB[n] = __ldg(&g_Kh[(size_t)srcs[n] * 64 + lane + 32]);
            qhA[n] = __ldg(&g_Qh[(size_t)dsts[n] * 64 + lane]);
            qhB[n] = __ldg(&g_Qh[(size_t)dsts[n] * 64 + lane + 32]);
        }

        // phase A: load this warp's 4 edge rows (k-contiguous)
        #pragma unroll
        for (int n = 0; n < 4; n++) {
            size_t base = (size_t)(e0 + n) * 64;
            sEA[(e_loc0 + n) * EA_STRIDE + lane]      = edge_attr[base + lane];
            sEA[(e_loc0 + n) * EA_STRIDE + lane + 32] = edge_attr[base + lane + 32];
        }
        __syncwarp();

        // GEMM
        unsigned long long acc[4][4];
        #pragma unroll
        for (int e = 0; e < 4; e++) {
            acc[e][0] = bini0; acc[e][1] = bini1;
            acc[e][2] = bini2; acc[e][3] = bini3;
        }

        #pragma unroll 4
        for (int k4 = 0; k4 < 64; k4 += 4) {
            ulonglong2 ww0 = *reinterpret_cast<const ulonglong2*>(wrow0 + k4);
            ulonglong2 ww1 = *reinterpret_cast<const ulonglong2*>(wrow1 + k4);
            ulonglong2 ww2 = *reinterpret_cast<const ulonglong2*>(wrow2 + k4);
            ulonglong2 ww3 = *reinterpret_cast<const ulonglong2*>(wrow3 + k4);
            #pragma unroll
            for (int e = 0; e < 4; e++) {
                ulonglong2 aa = *reinterpret_cast<const ulonglong2*>(
                    &sEA[(e_loc0 + e) * EA_STRIDE + k4]);
                ffma2(acc[e][0], aa.x, ww0.x); ffma2(acc[e][0], aa.y, ww0.y);
                ffma2(acc[e][1], aa.x, ww1.x); ffma2(acc[e][1], aa.y, ww1.y);
                ffma2(acc[e][2], aa.x, ww2.x); ffma2(acc[e][2], aa.y, ww2.y);
                ffma2(acc[e][3], aa.x, ww3.x); ffma2(acc[e][3], aa.y, ww3.y);
            }
        }
        __syncwarp();   // attrs fully consumed before score stash overwrites

        // phase B: scores (global wE + smem stash), per-head exp, den atomics
        #pragma unroll
        for (int n = 0; n < 4; n++) {
            int e = e0 + n;
            int dst = dsts[n];
            float ew0 = sum2(acc[n][0]);
            float eb0 = sum2(acc[n][1]);
            float ew1 = sum2(acc[n][2]);
            float eb1 = sum2(acc[n][3]);

            float kq0 = khA[n] + qhA[n];
            float kq1 = khB[n] + qhB[n];
            float sc0 = signed_sqrt(kq0 * ew0) + eb0;
            float sc1 = signed_sqrt(kq1 * ew1) + eb1;

            wE_out[(size_t)e * 64 + lane]      = sc0;
            wE_out[(size_t)e * 64 + lane + 32] = sc1;
            float* srow = &sEA[(e_loc0 + n) * EA_STRIDE];
            srow[lane]      = sc0;
            srow[lane + 32] = sc1;

            float p0 = sc0 * aw0;
            float p1 = sc1 * aw1;
            #pragma unroll
            for (int off = 4; off > 0; off >>= 1) {
                p0 += __shfl_xor_sync(0xffffffffu, p0, off);
                p1 += __shfl_xor_sync(0xffffffffu, p1, off);
            }
            p0 = expf(fminf(fmaxf(p0, -CLAMP_V), CLAMP_V));
            p1 = expf(fminf(fmaxf(p1, -CLAMP_V), CLAMP_V));
            if (d0 == 0) {
                sP[warp][n][h0]     = p0;
                sP[warp][n][h0 + 4] = p1;
                atomicAdd(&g_den[(size_t)dst * 8 + h0],     p0);
                atomicAdd(&g_den[(size_t)dst * 8 + h0 + 4], p1);
            }
        }
        __syncwarp();

        // phase C: scatter unnormalized numerators.
        // lanes 0-15: exp*V -> g_wV; lanes 16-31: exp*e_t (smem) -> g_rowV
        const int q  = lane & 15;
        const int j0 = q * 4;
        const int hq = q >> 1;
        #pragma unroll
        for (int n = 0; n < 4; n++) {
            float p = sP[warp][n][hq];
            int dst = dsts[n];
            if (lane < 16) {
                float4 v = *reinterpret_cast<const float4*>(&g_Vh[(size_t)srcs[n] * 64 + j0]);
                redAddV4(&g_wV[(size_t)dst * 64 + j0], v.x * p, v.y * p, v.z * p, v.w * p);
            } else {
                float4 et = *reinterpret_cast<const float4*>(&sEA[(e_loc0 + n) * EA_STRIDE + j0]);
                redAddV4(&g_rowV[(size_t)dst * 64 + j0], et.x * p, et.y * p, et.z * p, et.w * p);
            }
        }
        __syncwarp();
    }
}

// ---------------- kernel 4: finalize wV = (wV_raw + rowV_raw @ VeRow) / den ----
__global__ void k_final(const float* __restrict__ VeRow, float* __restrict__ wV_out) {
    int i = blockIdx.x * blockDim.x + threadIdx.x;
    if (i >= N_NODES * HDIM) return;
    int n = i >> 6, j = i & 63;
    int h = j >> 3, c = j & 7;
    float inv = 1.0f / (g_den[(size_t)n * 8 + h] + 1e-16f);
    float acc = g_wV[i];
    const float* rv = &g_rowV[(size_t)n * 64 + h * 8];
    #pragma unroll
    for (int d = 0; d < 8; d++)
        acc = fmaf(rv[d], __ldg(&VeRow[d * 64 + h * 8 + c]), acc);
    wV_out[i] = acc * inv;
}

// ---------------- launch ----------------
extern "C" void kernel_launch(void* const* d_in, const int* in_sizes, int n_in,
                              void* d_out, int out_size) {
    const float* x         = (const float*)d_in[0];
    const float* edge_attr = (const float*)d_in[1];
    const void*  ei_raw    = d_in[2];
    const float* Wq = (const float*)d_in[3];
    const float* bq = (const float*)d_in[4];
    const float* Wk = (const float*)d_in[5];
    const float* bk = (const float*)d_in[6];
    const float* We = (const float*)d_in[7];
    const float* be = (const float*)d_in[8];
    const float* Wv = (const float*)d_in[9];
    const float* bv = (const float*)d_in[10];
    const float* Aw = (const float*)d_in[11];
    const float* VeRow = (const float*)d_in[12];

    float* out    = (float*)d_out;
    float* wV_out = out;
    float* wE_out = out + (size_t)N_NODES * HDIM;

    cudaFuncSetAttribute(k_edge, cudaFuncAttributeMaxDynamicSharedMemorySize,
                         SMEM_EDGE_BYTES);

    k_init<<<(N_NODES * HDIM / 4 + 255) / 256, 256>>>();
    k_detect<<<(N_EDGES + 255) / 256, 256>>>((const unsigned*)ei_raw);
    k_nodeproj<<<(N_NODES + 31) / 32, 256>>>(x, Wq, bq, Wk, bk, Wv, bv);
    k_edge<<<EDGE_GRID, 256, SMEM_EDGE_BYTES>>>(edge_attr, ei_raw, We, be, Aw, wE_out);
    k_final<<<(N_NODES * HDIM + 255) / 256, 256>>>(VeRow, wV_out);
}

// round 7
// speedup vs baseline: 1.1605x; 1.1605x over previous
#include <cuda_runtime.h>
#include <math.h>
#include <stdint.h>

#define N_NODES 50000
#define N_EDGES 800000
#define HEADS   8
#define ODIM    8
#define HDIM    64
#define CLAMP_V 5.0f
#define EPS_V   1e-8f
#define TILES   (N_EDGES / 32)      // 25000 tiles of 32 edges
#define EDGE_GRID 444               // 148 SMs * 3 persistent blocks

#define W_STRIDE  68                // sWT row stride in floats (272B, 16B-aligned)
#define EA_STRIDE 68                // sEA row stride (attrs, then scores)
#define SMEM_WT_FLOATS (128 * W_STRIDE)
#define SMEM_EA_FLOATS (32 * EA_STRIDE)
#define SMEM_KQ_FLOATS (8 * 4 * 4 * 32)      // [warp][edge][type][lane] = 4096
#define SMEM_EDGE_BYTES ((SMEM_WT_FLOATS + SMEM_EA_FLOATS + SMEM_KQ_FLOATS) * 4) // 59904

// ---------------- device scratch ----------------
__device__ __align__(16) float g_Qh[N_NODES * HDIM];
__device__ __align__(16) float g_Kh[N_NODES * HDIM];
__device__ __align__(16) float g_Vh[N_NODES * HDIM];
__device__ __align__(16) float g_den[N_NODES * HEADS];
__device__ __align__(16) float g_wV  [N_NODES * HDIM];
__device__ __align__(16) float g_rowV[N_NODES * HDIM];
__device__ unsigned g_orhigh;

// ---------------- helpers ----------------
__device__ __forceinline__ void redAddV4(float* p, float a, float b, float c, float d) {
    asm volatile("red.global.add.v4.f32 [%0], {%1,%2,%3,%4};"
                 :: "l"(p), "f"(a), "f"(b), "f"(c), "f"(d) : "memory");
}
__device__ __forceinline__ void ffma2(unsigned long long& acc,
                                      unsigned long long a, unsigned long long b) {
    asm("fma.rn.f32x2 %0, %1, %2, %0;" : "+l"(acc) : "l"(a), "l"(b));
}
__device__ __forceinline__ unsigned long long pack2(float lo, float hi) {
    unsigned long long r;
    asm("mov.b64 %0, {%1,%2};" : "=l"(r) : "f"(lo), "f"(hi));
    return r;
}
__device__ __forceinline__ float sum2(unsigned long long v) {
    float2 r;
    asm("mov.b64 {%0,%1}, %2;" : "=f"(r.x), "=f"(r.y) : "l"(v));
    return r.x + r.y;
}
__device__ __forceinline__ float fsqrt_ap(float x) {
    float r; asm("sqrt.approx.f32 %0, %1;" : "=f"(r) : "f"(x)); return r;
}
__device__ __forceinline__ float signed_sqrt(float x) {
    return fsqrt_ap(fmaxf(x, 0.0f) + EPS_V) - fsqrt_ap(fmaxf(-x, 0.0f) + EPS_V);
}
__device__ __forceinline__ void cp_async4(uint32_t smem_addr, const void* gptr) {
    asm volatile("cp.async.ca.shared.global [%0], [%1], 4;"
                 :: "r"(smem_addr), "l"(gptr));
}
__device__ __forceinline__ void cp_async_wait_all() {
    asm volatile("cp.async.wait_all;" ::: "memory");
}

// ---------------- kernel 0: init accumulators + dtype flag ----------------
__global__ void k_init() {
    int i = blockIdx.x * blockDim.x + threadIdx.x;
    float4 z = make_float4(0.f, 0.f, 0.f, 0.f);
    if (i < N_NODES * HDIM / 4) {
        reinterpret_cast<float4*>(g_wV)[i] = z;
        reinterpret_cast<float4*>(g_rowV)[i] = z;
    }
    if (i < N_NODES * HEADS / 4) reinterpret_cast<float4*>(g_den)[i] = z;
    if (i == 0) g_orhigh = 0u;
}

// ---------------- kernel 1: index dtype detection ----------------
__global__ void k_detect(const unsigned* __restrict__ raw) {
    int i = blockIdx.x * blockDim.x + threadIdx.x;
    unsigned hi = (i < N_EDGES) ? raw[2 * i + 1] : 0u;
    hi = __reduce_or_sync(0xffffffffu, hi);
    if ((threadIdx.x & 31) == 0 && hi) atomicOr(&g_orhigh, hi);
}

// ---------------- kernel 2: node projections Q,K,V ----------------
__global__ void k_nodeproj(const float* __restrict__ x,
                           const float* __restrict__ Wq, const float* __restrict__ bq,
                           const float* __restrict__ Wk, const float* __restrict__ bk,
                           const float* __restrict__ Wv, const float* __restrict__ bv) {
    __shared__ float sW[64 * 64];
    __shared__ float sA[8][4][64];
    const int tid = threadIdx.x, warp = tid >> 5, lane = tid & 31;
    const int n0 = (blockIdx.x * 8 + warp) * 4;

    #pragma unroll
    for (int n = 0; n < 4; n++) {
        int node = n0 + n; if (node >= N_NODES) node = N_NODES - 1;
        sA[warp][n][lane]      = x[(size_t)node * 64 + lane];
        sA[warp][n][lane + 32] = x[(size_t)node * 64 + lane + 32];
    }

#define PROJ(W, B, OUT) do {                                                  \
    __syncthreads();                                                          \
    for (int i = tid; i < 4096; i += 256) sW[i] = (W)[i];                     \
    __syncthreads();                                                          \
    float b0 = (B)[lane], b1 = (B)[lane + 32];                                \
    float a0c0 = b0, a0c1 = b1, a1c0 = b0, a1c1 = b1;                         \
    float a2c0 = b0, a2c1 = b1, a3c0 = b0, a3c1 = b1;                         \
    _Pragma("unroll 16")                                                      \
    for (int k = 0; k < 64; k++) {                                            \
        float w0 = sW[k * 64 + lane], w1 = sW[k * 64 + lane + 32];            \
        float a0 = sA[warp][0][k], a1 = sA[warp][1][k];                       \
        float a2 = sA[warp][2][k], a3 = sA[warp][3][k];                       \
        a0c0 = fmaf(a0, w0, a0c0); a0c1 = fmaf(a0, w1, a0c1);                 \
        a1c0 = fmaf(a1, w0, a1c0); a1c1 = fmaf(a1, w1, a1c1);                 \
        a2c0 = fmaf(a2, w0, a2c0); a2c1 = fmaf(a2, w1, a2c1);                 \
        a3c0 = fmaf(a3, w0, a3c0); a3c1 = fmaf(a3, w1, a3c1);                 \
    }                                                                         \
    if (n0 + 0 < N_NODES) { (OUT)[(size_t)(n0+0)*64+lane]=a0c0; (OUT)[(size_t)(n0+0)*64+lane+32]=a0c1; } \
    if (n0 + 1 < N_NODES) { (OUT)[(size_t)(n0+1)*64+lane]=a1c0; (OUT)[(size_t)(n0+1)*64+lane+32]=a1c1; } \
    if (n0 + 2 < N_NODES) { (OUT)[(size_t)(n0+2)*64+lane]=a2c0; (OUT)[(size_t)(n0+2)*64+lane+32]=a2c1; } \
    if (n0 + 3 < N_NODES) { (OUT)[(size_t)(n0+3)*64+lane]=a3c0; (OUT)[(size_t)(n0+3)*64+lane+32]=a3c1; } \
} while (0)

    PROJ(Wq, bq, g_Qh);
    PROJ(Wk, bk, g_Kh);
    PROJ(Wv, bv, g_Vh);
#undef PROJ
}

// ---------------- kernel 3: fused edge kernel ----------------
// Kh/Qh gathers prefetched via cp.async into smem (zero register cost),
// issued before the GEMM so their latency hides under FFMA2 work.
// GEMM: FFMA2 lanes = (even-k, odd-k) partial sums; lane computes exactly its
// phase-B columns cw, cw+8, cw+64, cw+72 (cw=(lane>>3)*16+(lane&7)).
__global__ void __launch_bounds__(256, 3)
k_edge(const float* __restrict__ edge_attr,
       const void* __restrict__ ei_raw,
       const float* __restrict__ We, const float* __restrict__ be,
       const float* __restrict__ Aw,
       float* __restrict__ wE_out) {
    extern __shared__ float smem[];
    float* sWT = smem;                                   // [128][W_STRIDE]
    float* sEA = smem + SMEM_WT_FLOATS;                  // [32][EA_STRIDE]
    float* sKQ = smem + SMEM_WT_FLOATS + SMEM_EA_FLOATS; // [8][4][4][32]
    __shared__ float sP[8][4][8];                        // exp(s) per (warp, edge, head)

    const int tid = threadIdx.x, warp = tid >> 5, lane = tid & 31;
    const int e_loc0 = warp * 4;

    // one-time: transpose We into sWT
    for (int i = tid; i < 128 * 64; i += 256) {
        int c = i & 127, k = i >> 7;
        sWT[c * W_STRIDE + k] = We[k * 128 + c];
    }
    __syncthreads();

    const int d0 = lane & 7, h0 = lane >> 3;
    const int cw = (h0 << 4) + d0;
    const float aw0 = Aw[d0 * 8 + h0];
    const float aw1 = Aw[d0 * 8 + h0 + 4];

    const unsigned long long bini0 = pack2(be[cw],      0.f);
    const unsigned long long bini1 = pack2(be[cw + 8],  0.f);
    const unsigned long long bini2 = pack2(be[cw + 64], 0.f);
    const unsigned long long bini3 = pack2(be[cw + 72], 0.f);

    const float* wrow0 = &sWT[(cw)      * W_STRIDE];
    const float* wrow1 = &sWT[(cw + 8)  * W_STRIDE];
    const float* wrow2 = &sWT[(cw + 64) * W_STRIDE];
    const float* wrow3 = &sWT[(cw + 72) * W_STRIDE];

    const bool idx64 = (g_orhigh == 0u);
    const long long* p64 = (const long long*)ei_raw;
    const int*       p32 = (const int*)ei_raw;

    // base smem byte address of this warp's sKQ slot for cp.async
    const uint32_t kq_base = (uint32_t)__cvta_generic_to_shared(
        &sKQ[(warp * 4) * 4 * 32 + lane]);

    for (int tile = blockIdx.x; tile < TILES; tile += gridDim.x) {
        const int e0 = tile * 32 + e_loc0;

        // ---- indices ----
        int srcs[4], dsts[4];
        if (idx64) {
            #pragma unroll
            for (int n = 0; n < 4; n++) {
                srcs[n] = (int)__ldg(&p64[e0 + n]);
                dsts[n] = (int)__ldg(&p64[N_EDGES + e0 + n]);
            }
        } else {
            #pragma unroll
            for (int n = 0; n < 4; n++) {
                srcs[n] = __ldg(&p32[e0 + n]);
                dsts[n] = __ldg(&p32[N_EDGES + e0 + n]);
            }
        }

        // ---- async prefetch of Kh/Qh lane values (covered by GEMM) ----
        #pragma unroll
        for (int n = 0; n < 4; n++) {
            uint32_t b = kq_base + (uint32_t)(n * 4 * 32) * 4u;
            cp_async4(b,            &g_Kh[(size_t)srcs[n] * 64 + lane]);
            cp_async4(b + 128,      &g_Kh[(size_t)srcs[n] * 64 + lane + 32]);
            cp_async4(b + 256,      &g_Qh[(size_t)dsts[n] * 64 + lane]);
            cp_async4(b + 384,      &g_Qh[(size_t)dsts[n] * 64 + lane + 32]);
        }

        // phase A: load this warp's 4 edge rows (k-contiguous)
        #pragma unroll
        for (int n = 0; n < 4; n++) {
            size_t base = (size_t)(e0 + n) * 64;
            sEA[(e_loc0 + n) * EA_STRIDE + lane]      = edge_attr[base + lane];
            sEA[(e_loc0 + n) * EA_STRIDE + lane + 32] = edge_attr[base + lane + 32];
        }
        __syncwarp();

        // GEMM
        unsigned long long acc[4][4];
        #pragma unroll
        for (int e = 0; e < 4; e++) {
            acc[e][0] = bini0; acc[e][1] = bini1;
            acc[e][2] = bini2; acc[e][3] = bini3;
        }

        #pragma unroll 4
        for (int k4 = 0; k4 < 64; k4 += 4) {
            ulonglong2 ww0 = *reinterpret_cast<const ulonglong2*>(wrow0 + k4);
            ulonglong2 ww1 = *reinterpret_cast<const ulonglong2*>(wrow1 + k4);
            ulonglong2 ww2 = *reinterpret_cast<const ulonglong2*>(wrow2 + k4);
            ulonglong2 ww3 = *reinterpret_cast<const ulonglong2*>(wrow3 + k4);
            #pragma unroll
            for (int e = 0; e < 4; e++) {
                ulonglong2 aa = *reinterpret_cast<const ulonglong2*>(
                    &sEA[(e_loc0 + e) * EA_STRIDE + k4]);
                ffma2(acc[e][0], aa.x, ww0.x); ffma2(acc[e][0], aa.y, ww0.y);
                ffma2(acc[e][1], aa.x, ww1.x); ffma2(acc[e][1], aa.y, ww1.y);
                ffma2(acc[e][2], aa.x, ww2.x); ffma2(acc[e][2], aa.y, ww2.y);
                ffma2(acc[e][3], aa.x, ww3.x); ffma2(acc[e][3], aa.y, ww3.y);
            }
        }
        cp_async_wait_all();
        __syncwarp();   // attrs fully consumed before score stash overwrites

        // phase B: scores (stcs global wE + smem stash), per-head exp, den atomics
        const float* kq = &sKQ[(warp * 4) * 4 * 32 + lane];
        #pragma unroll
        for (int n = 0; n < 4; n++) {
            int e = e0 + n;
            int dst = dsts[n];
            float ew0 = sum2(acc[n][0]);
            float eb0 = sum2(acc[n][1]);
            float ew1 = sum2(acc[n][2]);
            float eb1 = sum2(acc[n][3]);

            float kq0 = kq[n * 128]       + kq[n * 128 + 64];
            float kq1 = kq[n * 128 + 32]  + kq[n * 128 + 96];
            float sc0 = signed_sqrt(kq0 * ew0) + eb0;
            float sc1 = signed_sqrt(kq1 * ew1) + eb1;

            __stcs(&wE_out[(size_t)e * 64 + lane],      sc0);
            __stcs(&wE_out[(size_t)e * 64 + lane + 32], sc1);
            float* srow = &sEA[(e_loc0 + n) * EA_STRIDE];
            srow[lane]      = sc0;
            srow[lane + 32] = sc1;

            float p0 = sc0 * aw0;
            float p1 = sc1 * aw1;
            #pragma unroll
            for (int off = 4; off > 0; off >>= 1) {
                p0 += __shfl_xor_sync(0xffffffffu, p0, off);
                p1 += __shfl_xor_sync(0xffffffffu, p1, off);
            }
            p0 = __expf(fminf(fmaxf(p0, -CLAMP_V), CLAMP_V));
            p1 = __expf(fminf(fmaxf(p1, -CLAMP_V), CLAMP_V));
            if (d0 == 0) {
                sP[warp][n][h0]     = p0;
                sP[warp][n][h0 + 4] = p1;
                atomicAdd(&g_den[(size_t)dst * 8 + h0],     p0);
                atomicAdd(&g_den[(size_t)dst * 8 + h0 + 4], p1);
            }
        }
        __syncwarp();

        // phase C: scatter unnormalized numerators.
        // lanes 0-15: exp*V -> g_wV; lanes 16-31: exp*e_t (smem) -> g_rowV
        const int q  = lane & 15;
        const int j0 = q * 4;
        const int hq = q >> 1;
        #pragma unroll
        for (int n = 0; n < 4; n++) {
            float p = sP[warp][n][hq];
            int dst = dsts[n];
            if (lane < 16) {
                float4 v = *reinterpret_cast<const float4*>(&g_Vh[(size_t)srcs[n] * 64 + j0]);
                redAddV4(&g_wV[(size_t)dst * 64 + j0], v.x * p, v.y * p, v.z * p, v.w * p);
            } else {
                float4 et = *reinterpret_cast<const float4*>(&sEA[(e_loc0 + n) * EA_STRIDE + j0]);
                redAddV4(&g_rowV[(size_t)dst * 64 + j0], et.x * p, et.y * p, et.z * p, et.w * p);
            }
        }
        __syncwarp();
    }
}

// ---------------- kernel 4: finalize wV = (wV_raw + rowV_raw @ VeRow) / den ----
__global__ void k_final(const float* __restrict__ VeRow, float* __restrict__ wV_out) {
    int i = blockIdx.x * blockDim.x + threadIdx.x;
    if (i >= N_NODES * HDIM) return;
    int n = i >> 6, j = i & 63;
    int h = j >> 3, c = j & 7;
    float inv = 1.0f / (g_den[(size_t)n * 8 + h] + 1e-16f);
    float acc = g_wV[i];
    const float* rv = &g_rowV[(size_t)n * 64 + h * 8];
    #pragma unroll
    for (int d = 0; d < 8; d++)
        acc = fmaf(rv[d], __ldg(&VeRow[d * 64 + h * 8 + c]), acc);
    wV_out[i] = acc * inv;
}

// ---------------- launch ----------------
extern "C" void kernel_launch(void* const* d_in, const int* in_sizes, int n_in,
                              void* d_out, int out_size) {
    const float* x         = (const float*)d_in[0];
    const float* edge_attr = (const float*)d_in[1];
    const void*  ei_raw    = d_in[2];
    const float* Wq = (const float*)d_in[3];
    const float* bq = (const float*)d_in[4];
    const float* Wk = (const float*)d_in[5];
    const float* bk = (const float*)d_in[6];
    const float* We = (const float*)d_in[7];
    const float* be = (const float*)d_in[8];
    const float* Wv = (const float*)d_in[9];
    const float* bv = (const float*)d_in[10];
    const float* Aw = (const float*)d_in[11];
    const float* VeRow = (const float*)d_in[12];

    float* out    = (float*)d_out;
    float* wV_out = out;
    float* wE_out = out + (size_t)N_NODES * HDIM;

    cudaFuncSetAttribute(k_edge, cudaFuncAttributeMaxDynamicSharedMemorySize,
                         SMEM_EDGE_BYTES);

    k_init<<<(N_NODES * HDIM / 4 + 255) / 256, 256>>>();
    k_detect<<<(N_EDGES + 255) / 256, 256>>>((const unsigned*)ei_raw);
    k_nodeproj<<<(N_NODES + 31) / 32, 256>>>(x, Wq, bq, Wk, bk, Wv, bv);
    k_edge<<<EDGE_GRID, 256, SMEM_EDGE_BYTES>>>(edge_attr, ei_raw, We, be, Aw, wE_out);
    k_final<<<(N_NODES * HDIM + 255) / 256, 256>>>(VeRow, wV_out);
}